// round 10
// baseline (speedup 1.0000x reference)
#include <cuda_runtime.h>
#include <cuda_bf16.h>

#define BS   256
#define MAXB 2048
#define EPS_IOU 1e-8f

__device__ float        g_partials[MAXB];
__device__ unsigned int g_done = 0;

__global__ void __launch_bounds__(BS)
RotatedIoU3DLoss_66769561583663_kernel(const float* __restrict__ pred,
                                       const float* __restrict__ tgt,
                                       float* __restrict__ out,
                                       int n, float inv_n)
{
    float acc = 0.0f;

    for (int i = blockIdx.x * BS + threadIdx.x; i < n; i += gridDim.x * BS) {
        const float* P = pred + (size_t)i * 7;
        const float* T = tgt  + (size_t)i * 7;
        float px = P[0], py = P[1], pz = P[2], pw = P[3], pl = P[4], ph = P[5], pa = P[6];
        float qx = T[0], qy = T[1], qz = T[2], qw = T[3], ql = T[4], qh = T[5], qa = T[6];

        // ---- corners of both boxes (CCW: (.5,.5),(-.5,.5),(-.5,-.5),(.5,-.5)) ----
        const float KX[4] = { 0.5f, -0.5f, -0.5f,  0.5f };
        const float KY[4] = { 0.5f,  0.5f, -0.5f, -0.5f };
        float c1x[4], c1y[4], c2x[4], c2y[4];
        {
            float ca, sa;
            sincosf(pa, &sa, &ca);
            #pragma unroll
            for (int k = 0; k < 4; k++) {
                float xx = KX[k] * pw, yy = KY[k] * pl;
                c1x[k] = xx * ca - yy * sa + px;
                c1y[k] = xx * sa + yy * ca + py;
            }
            sincosf(qa, &sa, &ca);
            #pragma unroll
            for (int k = 0; k < 4; k++) {
                float xx = KX[k] * qw, yy = KY[k] * ql;
                c2x[k] = xx * ca - yy * sa + qx;
                c2y[k] = xx * sa + yy * ca + qy;
            }
        }

        // ---- Sutherland–Hodgman: clip box1 (CCW) by box2's 4 half-planes ----
        float X[12], Y[12], NX[12], NY[12];
        int m = 4;
        #pragma unroll
        for (int k = 0; k < 4; k++) { X[k] = c1x[k]; Y[k] = c1y[k]; }

        #pragma unroll
        for (int e = 0; e < 4; e++) {
            float ax = c2x[e],           ay = c2y[e];
            float ex = c2x[(e + 1) & 3] - ax;
            float ey = c2y[(e + 1) & 3] - ay;

            int nm = 0;
            float xk = X[0], yk = Y[0];
            float dk = ex * (yk - ay) - ey * (xk - ax);   // >=0 : inside (left of edge)
            for (int k = 0; k < m; k++) {
                int k2 = (k + 1 == m) ? 0 : k + 1;
                float xn = X[k2], yn = Y[k2];
                float dn = ex * (yn - ay) - ey * (xn - ax);
                bool ik = (dk >= 0.0f), in_ = (dn >= 0.0f);
                if (ik) { NX[nm] = xk; NY[nm] = yk; nm++; }
                if (ik != in_) {
                    float t = dk / (dk - dn);
                    NX[nm] = xk + t * (xn - xk);
                    NY[nm] = yk + t * (yn - yk);
                    nm++;
                }
                xk = xn; yk = yn; dk = dn;
            }
            m = (nm > 12) ? 12 : nm;
            for (int k = 0; k < m; k++) { X[k] = NX[k]; Y[k] = NY[k]; }
            if (m == 0) break;
        }

        // ---- shoelace (polygon is in cyclic order; CCW -> positive) ----
        float area = 0.0f;
        if (m > 2) {
            float ssum = 0.0f;
            for (int k = 0; k < m; k++) {
                int k2 = (k + 1 == m) ? 0 : k + 1;
                ssum += X[k] * Y[k2] - Y[k] * X[k2];
            }
            area = 0.5f * fabsf(ssum);
        }

        // ---- z overlap, volumes, IoU ----
        float zt = fminf(pz + 0.5f * ph, qz + 0.5f * qh);
        float zb = fmaxf(pz - 0.5f * ph, qz - 0.5f * qh);
        float inter_vol = area * fmaxf(zt - zb, 0.0f);
        float v1 = pw * pl * ph;
        float v2 = qw * ql * qh;
        float iou = inter_vol / (v1 + v2 - inter_vol + EPS_IOU);
        acc += 1.0f - iou;
    }

    // ---- deterministic block reduction ----
    __shared__ float sd[BS];
    sd[threadIdx.x] = acc;
    __syncthreads();
    #pragma unroll
    for (int s = BS / 2; s > 0; s >>= 1) {
        if (threadIdx.x < s) sd[threadIdx.x] += sd[threadIdx.x + s];
        __syncthreads();
    }

    // ---- fused finalize: last block sums partials in fixed order ----
    __shared__ bool amLast;
    if (threadIdx.x == 0) {
        g_partials[blockIdx.x] = sd[0];
        __threadfence();
        unsigned int prev = atomicAdd(&g_done, 1u);
        amLast = (prev == gridDim.x - 1);
    }
    __syncthreads();

    if (amLast) {
        float s = 0.0f;
        for (int k = threadIdx.x; k < (int)gridDim.x; k += BS) s += g_partials[k];
        sd[threadIdx.x] = s;
        __syncthreads();
        #pragma unroll
        for (int st = BS / 2; st > 0; st >>= 1) {
            if (threadIdx.x < st) sd[threadIdx.x] += sd[threadIdx.x + st];
            __syncthreads();
        }
        if (threadIdx.x == 0) {
            out[0] = sd[0] * inv_n;
            g_done = 0;               // self-reset for next graph replay
        }
    }
}

extern "C" void kernel_launch(void* const* d_in, const int* in_sizes, int n_in,
                              void* d_out, int out_size)
{
    const float* pred = (const float*)d_in[0];
    const float* tgt  = (const float*)d_in[1];
    int n = in_sizes[0] / 7;

    int grid = (n + BS - 1) / BS;
    if (grid > MAXB) grid = MAXB;

    RotatedIoU3DLoss_66769561583663_kernel<<<grid, BS>>>(pred, tgt, (float*)d_out,
                                                         n, 1.0f / (float)n);
}

// round 12
// speedup vs baseline: 1.0316x; 1.0316x over previous
#include <cuda_runtime.h>
#include <cuda_bf16.h>

#define BS   256
#define MAXB 2048
#define EPS_IOU 1e-8f

__device__ float        g_partials[MAXB];
__device__ unsigned int g_done = 0;

__global__ void __launch_bounds__(BS)
RotatedIoU3DLoss_66769561583663_kernel(const float* __restrict__ pred,
                                       const float* __restrict__ tgt,
                                       float* __restrict__ out,
                                       int n, float inv_n)
{
    float acc = 0.0f;

    for (int i = blockIdx.x * BS + threadIdx.x; i < n; i += gridDim.x * BS) {
        const float* P = pred + (size_t)i * 7;
        const float* T = tgt  + (size_t)i * 7;
        float px = P[0], py = P[1], pz = P[2], pw = P[3], pl = P[4], ph = P[5], pa = P[6];
        float qx = T[0], qy = T[1], qz = T[2], qw = T[3], ql = T[4], qh = T[5], qa = T[6];

        // ---- corners of both boxes (CCW: (.5,.5),(-.5,.5),(-.5,-.5),(.5,-.5)) ----
        const float KX[4] = { 0.5f, -0.5f, -0.5f,  0.5f };
        const float KY[4] = { 0.5f,  0.5f, -0.5f, -0.5f };
        float c1x[4], c1y[4], c2x[4], c2y[4];
        {
            float ca, sa;
            sincosf(pa, &sa, &ca);
            #pragma unroll
            for (int k = 0; k < 4; k++) {
                float xx = KX[k] * pw, yy = KY[k] * pl;
                c1x[k] = xx * ca - yy * sa + px;
                c1y[k] = xx * sa + yy * ca + py;
            }
            sincosf(qa, &sa, &ca);
            #pragma unroll
            for (int k = 0; k < 4; k++) {
                float xx = KX[k] * qw, yy = KY[k] * ql;
                c2x[k] = xx * ca - yy * sa + qx;
                c2y[k] = xx * sa + yy * ca + qy;
            }
        }

        // ---- Sutherland–Hodgman: clip box1 (CCW) by box2's 4 half-planes ----
        float X[12], Y[12], NX[12], NY[12];
        int m = 4;
        #pragma unroll
        for (int k = 0; k < 4; k++) { X[k] = c1x[k]; Y[k] = c1y[k]; }

        #pragma unroll
        for (int e = 0; e < 4; e++) {
            float ax = c2x[e],           ay = c2y[e];
            float ex = c2x[(e + 1) & 3] - ax;
            float ey = c2y[(e + 1) & 3] - ay;

            int nm = 0;
            float xk = X[0], yk = Y[0];
            float dk = ex * (yk - ay) - ey * (xk - ax);   // >=0 : inside (left of edge)
            for (int k = 0; k < m; k++) {
                int k2 = (k + 1 == m) ? 0 : k + 1;
                float xn = X[k2], yn = Y[k2];
                float dn = ex * (yn - ay) - ey * (xn - ax);
                bool ik = (dk >= 0.0f), in_ = (dn >= 0.0f);
                if (ik) { NX[nm] = xk; NY[nm] = yk; nm++; }
                if (ik != in_) {
                    float t = dk / (dk - dn);
                    NX[nm] = xk + t * (xn - xk);
                    NY[nm] = yk + t * (yn - yk);
                    nm++;
                }
                xk = xn; yk = yn; dk = dn;
            }
            m = (nm > 12) ? 12 : nm;
            for (int k = 0; k < m; k++) { X[k] = NX[k]; Y[k] = NY[k]; }
            if (m == 0) break;
        }

        // ---- shoelace (polygon is in cyclic order; CCW -> positive) ----
        float area = 0.0f;
        if (m > 2) {
            float ssum = 0.0f;
            for (int k = 0; k < m; k++) {
                int k2 = (k + 1 == m) ? 0 : k + 1;
                ssum += X[k] * Y[k2] - Y[k] * X[k2];
            }
            area = 0.5f * fabsf(ssum);
        }

        // ---- z overlap, volumes, IoU ----
        float zt = fminf(pz + 0.5f * ph, qz + 0.5f * qh);
        float zb = fmaxf(pz - 0.5f * ph, qz - 0.5f * qh);
        float inter_vol = area * fmaxf(zt - zb, 0.0f);
        float v1 = pw * pl * ph;
        float v2 = qw * ql * qh;
        float iou = inter_vol / (v1 + v2 - inter_vol + EPS_IOU);
        acc += 1.0f - iou;
    }

    // ---- deterministic block reduction ----
    __shared__ float sd[BS];
    sd[threadIdx.x] = acc;
    __syncthreads();
    #pragma unroll
    for (int s = BS / 2; s > 0; s >>= 1) {
        if (threadIdx.x < s) sd[threadIdx.x] += sd[threadIdx.x + s];
        __syncthreads();
    }

    // ---- fused finalize: last block sums partials in fixed order ----
    __shared__ bool amLast;
    if (threadIdx.x == 0) {
        g_partials[blockIdx.x] = sd[0];
        __threadfence();
        unsigned int prev = atomicAdd(&g_done, 1u);
        amLast = (prev == gridDim.x - 1);
    }
    __syncthreads();

    if (amLast) {
        float s = 0.0f;
        for (int k = threadIdx.x; k < (int)gridDim.x; k += BS) s += g_partials[k];
        sd[threadIdx.x] = s;
        __syncthreads();
        #pragma unroll
        for (int st = BS / 2; st > 0; st >>= 1) {
            if (threadIdx.x < st) sd[threadIdx.x] += sd[threadIdx.x + st];
            __syncthreads();
        }
        if (threadIdx.x == 0) {
            out[0] = sd[0] * inv_n;
            g_done = 0;               // self-reset for next graph replay
        }
    }
}

extern "C" void kernel_launch(void* const* d_in, const int* in_sizes, int n_in,
                              void* d_out, int out_size)
{
    const float* pred = (const float*)d_in[0];
    const float* tgt  = (const float*)d_in[1];
    int n = in_sizes[0] / 7;

    int grid = (n + BS - 1) / BS;
    if (grid > MAXB) grid = MAXB;

    RotatedIoU3DLoss_66769561583663_kernel<<<grid, BS>>>(pred, tgt, (float*)d_out,
                                                         n, 1.0f / (float)n);
}